// round 15
// baseline (speedup 1.0000x reference)
#include <cuda_runtime.h>
#include <cuda_fp16.h>
#include <math.h>
#include <stdint.h>

// Problem constants (fixed by the dataset)
#define TT   4096
#define HD   1024
#define FD   4096
#define NE   8
#define KSEL 2
#define NSLOTS (TT * KSEL)
#define NSP   9216            // padded slots: 8192 + 8*128 headroom
#define SBLK  (NSP / 16)      // 576 slot blocks of 16
#define KB1   (HD / 16)       // 64  k16-blocks for GEMM1
#define NB1   (FD / 8)        // 512 n8-blocks  for GEMM1 weights
#define KB2   (FD / 16)       // 256 k16-blocks for GEMM2
#define NB2   (HD / 8)        // 128 n8-blocks  for GEMM2 weights

// ---------------- static scratch ----------------
__device__ int   d_count[NE];
__device__ int   d_fill[NE];
__device__ int   d_offset[NE];            // padded (multiple of 128) cumsum
__device__ int   d_rows[NSP];             // slot -> token (0 for padding)
__device__ float d_swgt[NSP];             // slot -> combine weight (0 for padding)
__device__ int   d_tope[TT * KSEL];
__device__ float d_tok_w[TT * KSEL];      // per-token top-k weights (router -> assign)
// fragment-major fp16 tensors (each uint4/uint2 = one lane's mma fragment)
__device__ __align__(16) uint4 d_xh [(size_t)SBLK * KB1 * 32];        // A frags G1
__device__ __align__(16) uint2 d_w1h[(size_t)NE * NB1 * KB1 * 32];    // B frags G1
__device__ __align__(16) uint2 d_w3h[(size_t)NE * NB1 * KB1 * 32];
__device__ __align__(16) uint4 d_ih [(size_t)SBLK * KB2 * 32];        // A frags G2 (inter)
__device__ __align__(16) uint2 d_w2h[(size_t)NE * NB2 * KB2 * 32];    // B frags G2

// ---------------- PTX helpers ----------------
__device__ __forceinline__ uint32_t smem_u32(const void* p) {
    uint32_t a;
    asm("{ .reg .u64 t; cvta.to.shared.u64 t, %1; cvt.u32.u64 %0, t; }" : "=r"(a) : "l"(p));
    return a;
}
#define CP16(s, g) \
    asm volatile("cp.async.cg.shared.global [%0], [%1], 16;" :: "r"(s), "l"(g) : "memory")
#define CPCOMMIT() asm volatile("cp.async.commit_group;" ::: "memory")
#define CPWAIT1()  asm volatile("cp.async.wait_group 1;" ::: "memory")
#define CPWAIT0()  asm volatile("cp.async.wait_group 0;" ::: "memory")

__device__ __forceinline__ uint32_t h2u(float a, float b) {
    __half2 h = __floats2half2_rn(a, b);
    return *reinterpret_cast<uint32_t*>(&h);
}

// D += A*B, m16n8k16 fp16 in / fp32 accum
__device__ __forceinline__ void mma16(float* c, uint32_t a0, uint32_t a1, uint32_t a2,
                                      uint32_t a3, uint32_t b0, uint32_t b1) {
    asm volatile(
        "mma.sync.aligned.m16n8k16.row.col.f32.f16.f16.f32 "
        "{%0,%1,%2,%3}, {%4,%5,%6,%7}, {%8,%9}, {%0,%1,%2,%3};"
        : "+f"(c[0]), "+f"(c[1]), "+f"(c[2]), "+f"(c[3])
        : "r"(a0), "r"(a1), "r"(a2), "r"(a3), "r"(b0), "r"(b1));
}

__device__ __forceinline__ float silu_mul(float v, float g) {
    return v / (1.f + __expf(-v)) * g;
}

// ---------------- prepass: fp32 weights -> fp16 fragment-major ----------------
__global__ void conv_w_kernel(const float* __restrict__ W, uint2* __restrict__ out,
                              int NBLK, int KBLK) {
    int idx  = blockIdx.x * 256 + threadIdx.x;       // over NE*NBLK*KBLK*32
    int lane = idx & 31;
    int rest = idx >> 5;
    int kb   = rest % KBLK;
    int nb   = (rest / KBLK) % NBLK;
    int e    = rest / (KBLK * NBLK);
    if (e >= NE) return;
    int gid = lane >> 2, tig = lane & 3;
    int K   = KBLK * 16;
    size_t row = (size_t)(e * NBLK + nb) * 8 + gid;
    int c   = kb * 16 + 2 * tig;
    float2 v0 = *reinterpret_cast<const float2*>(W + row * K + c);
    float2 v1 = *reinterpret_cast<const float2*>(W + row * K + c + 8);
    uint2 o;
    o.x = h2u(v0.x, v0.y);
    o.y = h2u(v1.x, v1.y);
    out[(size_t)idx] = o;
}

// ---------------- routing kernels ----------------
// merged zero: counters, slot maps, AND the output tensor (atomic scatter target)
__global__ void zero_all_kernel(float4* __restrict__ out4) {
    int i = blockIdx.x * blockDim.x + threadIdx.x;
    if (i < NE) { d_count[i] = 0; d_fill[i] = 0; }
    if (i < NSP) { d_rows[i] = 0; d_swgt[i] = 0.f; }
    if (i < TT * (HD / 4)) out4[i] = make_float4(0.f, 0.f, 0.f, 0.f);
}

__global__ void router_kernel(const float* __restrict__ x,
                              const float* __restrict__ gw,
                              float* __restrict__ logits_out) {
    int t    = blockIdx.x;
    int warp = threadIdx.x >> 5;
    int lane = threadIdx.x & 31;
    const float* xr = x + (size_t)t * HD;
    const float* gr = gw + (size_t)warp * HD;
    float s = 0.f;
    #pragma unroll 8
    for (int i = lane; i < HD; i += 32) s += xr[i] * gr[i];
    #pragma unroll
    for (int o = 16; o; o >>= 1) s += __shfl_xor_sync(0xffffffffu, s, o);
    __shared__ float sl[NE];
    if (lane == 0) sl[warp] = s;
    __syncthreads();
    if (threadIdx.x < NE) logits_out[(size_t)t * NE + threadIdx.x] = sl[threadIdx.x];
    if (threadIdx.x == 0) {
        float mx = sl[0];
        #pragma unroll
        for (int e = 1; e < NE; e++) mx = fmaxf(mx, sl[e]);
        float p[NE];
        #pragma unroll
        for (int e = 0; e < NE; e++) p[e] = expf(sl[e] - mx);
        int e0 = 0;
        #pragma unroll
        for (int e = 1; e < NE; e++) if (p[e] > p[e0]) e0 = e;
        int e1 = (e0 == 0) ? 1 : 0;
        #pragma unroll
        for (int e = 0; e < NE; e++) { if (e == e0) continue; if (p[e] > p[e1]) e1 = e; }
        float w0 = p[e0], w1 = p[e1];
        float ws = w0 + w1;
        w0 /= ws; w1 /= ws;
        d_tope[t * 2 + 0] = e0; d_tope[t * 2 + 1] = e1;
        d_tok_w[t * 2 + 0] = w0;
        d_tok_w[t * 2 + 1] = w1;
        atomicAdd(&d_count[e0], 1);
        atomicAdd(&d_count[e1], 1);
    }
}

__global__ void offsets_kernel() {
    if (threadIdx.x == 0) {
        int acc = 0;
        #pragma unroll
        for (int e = 0; e < NE; e++) {
            d_offset[e] = acc;
            acc += (d_count[e] + 127) & ~127;   // pad to 128 -> guard-free GEMMs
        }
    }
}

__global__ void assign_kernel() {
    int t = blockIdx.x * blockDim.x + threadIdx.x;
    if (t >= TT) return;
    #pragma unroll
    for (int k = 0; k < KSEL; k++) {
        int e = d_tope[t * 2 + k];
        int pos = atomicAdd(&d_fill[e], 1);
        int s = d_offset[e] + pos;
        d_rows[s] = t;
        d_swgt[s] = d_tok_w[t * 2 + k];
    }
}

// gather x into A-fragment-major fp16, slot order (padding slots read token 0)
__global__ void gather_x_kernel(const float* __restrict__ x) {
    int idx  = blockIdx.x * 256 + threadIdx.x;    // over SBLK*KB1*32
    if (idx >= SBLK * KB1 * 32) return;
    int lane = idx & 31;
    int kb   = (idx >> 5) % KB1;
    int sb   = (idx >> 5) / KB1;
    int gid = lane >> 2, tig = lane & 3;
    int t0 = d_rows[sb * 16 + gid];
    int t1 = d_rows[sb * 16 + gid + 8];
    int c  = kb * 16 + 2 * tig;
    float2 v00 = *reinterpret_cast<const float2*>(x + (size_t)t0 * HD + c);
    float2 v10 = *reinterpret_cast<const float2*>(x + (size_t)t1 * HD + c);
    float2 v01 = *reinterpret_cast<const float2*>(x + (size_t)t0 * HD + c + 8);
    float2 v11 = *reinterpret_cast<const float2*>(x + (size_t)t1 * HD + c + 8);
    uint4 o;
    o.x = h2u(v00.x, v00.y);
    o.y = h2u(v10.x, v10.y);
    o.z = h2u(v01.x, v01.y);
    o.w = h2u(v11.x, v11.y);
    d_xh[(size_t)idx] = o;
}

// =================== GEMM1: fp16 m16n8k16, fused SiLU·mul =================
// CTA 128 thr = 4 warps (2x2), CTA tile 128(M) x 64(N), warp tile 64x32 dual.
// Cross-warp smem duplication A*2 + B*2 = 64KB/stage (was 96KB with 8 warps).
#define G1_STG  32768
#define G1_AOFF 0
#define G1_B1OFF 16384
#define G1_B3OFF 24576
#define G1_SMEM (3 * G1_STG)
#define G1_NST  (HD / 64)     // 16 stages

__device__ __forceinline__ void g1_load(uint32_t sb, int st, int ks0, int tid,
                                        int sblk0, int e, int nb0) {
    uint32_t ab = sb + (uint32_t)st * G1_STG;
    #pragma unroll
    for (int i = 0; i < 8; i++) {                 // A: 1024 chunks of 16B
        int c = tid + i * 128;
        int lane = c & 31, lkb = (c >> 5) & 3, lsb = c >> 7;
        CP16(ab + G1_AOFF + c * 16,
             (const char*)(d_xh + (size_t)(((sblk0 + lsb) * KB1 + ks0 + lkb) * 32 + lane)));
    }
    #pragma unroll
    for (int i = 0; i < 4; i++) {                 // B1/B3: 512 chunks each
        int c = tid + i * 128;
        int inner = c & 15, b = c >> 4;
        int lk = b & 3, ln = b >> 2;
        size_t gidx = (size_t)(((e * NB1 + nb0 + ln) * KB1 + ks0 + lk) * 32) + inner * 2;
        CP16(ab + G1_B1OFF + c * 16, (const char*)(d_w1h + gidx));
        CP16(ab + G1_B3OFF + c * 16, (const char*)(d_w3h + gidx));
    }
    CPCOMMIT();
}

__global__ void __launch_bounds__(128, 2)
gemm1_mma() {
    int e  = blockIdx.z;
    int nt = blockIdx.y;                   // 64-col tile (slow axis)
    int m0 = blockIdx.x * 128;             // M-tile fastest -> L2 weight reuse
    int cnt  = d_count[e];
    int pcnt = (cnt + 127) & ~127;
    if (m0 >= pcnt) return;
    int base  = d_offset[e];
    int sblk0 = (base + m0) >> 4;
    int nb0   = nt * 8;

    extern __shared__ char smem[];
    uint32_t sb = smem_u32(smem);

    int tid = threadIdx.x;
    int wid = tid >> 5, lane = tid & 31;
    int wm = wid & 1, wn = wid >> 1;       // 2x2 warp grid
    int gid = lane >> 2, tig = lane & 3;

    float acc1[4][4][4], acc3[4][4][4];
    #pragma unroll
    for (int i = 0; i < 4; i++)
        #pragma unroll
        for (int j = 0; j < 4; j++)
            #pragma unroll
            for (int k = 0; k < 4; k++) { acc1[i][j][k] = 0.f; acc3[i][j][k] = 0.f; }

    g1_load(sb, 0, 0, tid, sblk0, e, nb0);
    g1_load(sb, 1, 4, tid, sblk0, e, nb0);

    for (int s = 0; s < G1_NST; s++) {
        if (s + 1 < G1_NST) CPWAIT1(); else CPWAIT0();
        __syncthreads();
        if (s + 2 < G1_NST) g1_load(sb, (s + 2) % 3, (s + 2) * 4, tid, sblk0, e, nb0);

        const char* st = smem + (size_t)(s % 3) * G1_STG;
        #pragma unroll
        for (int kk = 0; kk < 4; kk++) {
            uint4 a[4];
            #pragma unroll
            for (int mf = 0; mf < 4; mf++)
                a[mf] = *reinterpret_cast<const uint4*>(
                    st + G1_AOFF + (size_t)((((wm * 4 + mf) * 4 + kk) * 32 + lane)) * 16);
            uint2 b1[4], b3[4];
            #pragma unroll
            for (int nf = 0; nf < 4; nf++) {
                size_t bo = (size_t)((((wn * 4 + nf) * 4 + kk) * 32 + lane)) * 8;
                b1[nf] = *reinterpret_cast<const uint2*>(st + G1_B1OFF + bo);
                b3[nf] = *reinterpret_cast<const uint2*>(st + G1_B3OFF + bo);
            }
            #pragma unroll
            for (int nf = 0; nf < 4; nf++)
                #pragma unroll
                for (int mf = 0; mf < 4; mf++) {
                    mma16(acc1[mf][nf], a[mf].x, a[mf].y, a[mf].z, a[mf].w, b1[nf].x, b1[nf].y);
                    mma16(acc3[mf][nf], a[mf].x, a[mf].y, a[mf].z, a[mf].w, b3[nf].x, b3[nf].y);
                }
        }
        __syncthreads();
    }

    // epilogue: SiLU(h1)*h3 -> fp16, stored directly as GEMM2 A-fragments
    #pragma unroll
    for (int mf = 0; mf < 4; mf++) {
        int sblk = sblk0 + wm * 4 + mf;
        #pragma unroll
        for (int p = 0; p < 2; p++) {
            int nf0 = 2 * p, nf1 = 2 * p + 1;
            int kblkg = nt * 4 + wn * 2 + p;
            uint4 o;
            o.x = h2u(silu_mul(acc1[mf][nf0][0], acc3[mf][nf0][0]),
                      silu_mul(acc1[mf][nf0][1], acc3[mf][nf0][1]));
            o.y = h2u(silu_mul(acc1[mf][nf0][2], acc3[mf][nf0][2]),
                      silu_mul(acc1[mf][nf0][3], acc3[mf][nf0][3]));
            o.z = h2u(silu_mul(acc1[mf][nf1][0], acc3[mf][nf1][0]),
                      silu_mul(acc1[mf][nf1][1], acc3[mf][nf1][1]));
            o.w = h2u(silu_mul(acc1[mf][nf1][2], acc3[mf][nf1][2]),
                      silu_mul(acc1[mf][nf1][3], acc3[mf][nf1][3]));
            d_ih[(size_t)((sblk * KB2 + kblkg) * 32 + lane)] = o;
        }
    }
}

// =================== GEMM2: fp16 m16n8k16, fused weighted scatter ==========
// CTA 128 thr = 4 warps (2x2), CTA tile 128x128, warp tile 64x64.
// smem duplication A*2 + B*2 = 64KB/stage (was 96KB).
#define G2_STG  32768
#define G2_AOFF 0
#define G2_BOFF 16384
#define G2_SMEM (3 * G2_STG)
#define G2_NST  (FD / 64)     // 64 stages

__device__ __forceinline__ void g2_load(uint32_t sb, int st, int ks0, int tid,
                                        int sblk0, int e, int nb0) {
    uint32_t ab = sb + (uint32_t)st * G2_STG;
    #pragma unroll
    for (int i = 0; i < 8; i++) {                 // A: 1024 chunks
        int c = tid + i * 128;
        int lane = c & 31, lkb = (c >> 5) & 3, lsb = c >> 7;
        CP16(ab + G2_AOFF + c * 16,
             (const char*)(d_ih + (size_t)(((sblk0 + lsb) * KB2 + ks0 + lkb) * 32 + lane)));
    }
    #pragma unroll
    for (int i = 0; i < 8; i++) {                 // B: 1024 chunks (16 nblk x 4 kblk)
        int c = tid + i * 128;
        int inner = c & 15, b = c >> 4;
        int lk = b & 3, ln = b >> 2;
        size_t gidx = (size_t)(((e * NB2 + nb0 + ln) * KB2 + ks0 + lk) * 32) + inner * 2;
        CP16(ab + G2_BOFF + c * 16, (const char*)(d_w2h + gidx));
    }
    CPCOMMIT();
}

__global__ void __launch_bounds__(128, 2)
gemm2_mma(float* __restrict__ out) {
    int e  = blockIdx.z;
    int nt = blockIdx.y;                   // 128-col tile (slow)
    int m0 = blockIdx.x * 128;             // M-tile fastest
    int cnt  = d_count[e];
    int pcnt = (cnt + 127) & ~127;
    if (m0 >= pcnt) return;
    int base  = d_offset[e];
    int sblk0 = (base + m0) >> 4;
    int nb0   = nt * 16;

    extern __shared__ char smem[];
    uint32_t sb = smem_u32(smem);

    int tid = threadIdx.x;
    int wid = tid >> 5, lane = tid & 31;
    int wm = wid & 1, wn = wid >> 1;       // 2x2 warp grid
    int gid = lane >> 2, tig = lane & 3;

    float acc[4][8][4];
    #pragma unroll
    for (int i = 0; i < 4; i++)
        #pragma unroll
        for (int j = 0; j < 8; j++)
            #pragma unroll
            for (int k = 0; k < 4; k++) acc[i][j][k] = 0.f;

    g2_load(sb, 0, 0, tid, sblk0, e, nb0);
    g2_load(sb, 1, 4, tid, sblk0, e, nb0);

    for (int s = 0; s < G2_NST; s++) {
        if (s + 1 < G2_NST) CPWAIT1(); else CPWAIT0();
        __syncthreads();
        if (s + 2 < G2_NST) g2_load(sb, (s + 2) % 3, (s + 2) * 4, tid, sblk0, e, nb0);

        const char* st = smem + (size_t)(s % 3) * G2_STG;
        #pragma unroll
        for (int kk = 0; kk < 4; kk++) {
            uint4 a[4];
            #pragma unroll
            for (int mf = 0; mf < 4; mf++)
                a[mf] = *reinterpret_cast<const uint4*>(
                    st + G2_AOFF + (size_t)((((wm * 4 + mf) * 4 + kk) * 32 + lane)) * 16);
            uint2 b[8];
            #pragma unroll
            for (int nf = 0; nf < 8; nf++)
                b[nf] = *reinterpret_cast<const uint2*>(
                    st + G2_BOFF + (size_t)((((wn * 8 + nf) * 4 + kk) * 32 + lane)) * 8);
            #pragma unroll
            for (int nf = 0; nf < 8; nf++)
                #pragma unroll
                for (int mf = 0; mf < 4; mf++)
                    mma16(acc[mf][nf], a[mf].x, a[mf].y, a[mf].z, a[mf].w, b[nf].x, b[nf].y);
        }
        __syncthreads();
    }

    // fused combine: weighted atomic scatter to out[token]
    #pragma unroll
    for (int mf = 0; mf < 4; mf++) {
        int r  = base + m0 + wm * 64 + mf * 16 + gid;
        int t0 = d_rows[r],     t1 = d_rows[r + 8];
        float w0 = d_swgt[r],   w1 = d_swgt[r + 8];
        #pragma unroll
        for (int nf = 0; nf < 8; nf++) {
            int n = nt * 128 + wn * 64 + nf * 8 + 2 * tig;
            if (w0 != 0.f) {
                atomicAdd(&out[(size_t)t0 * HD + n],     w0 * acc[mf][nf][0]);
                atomicAdd(&out[(size_t)t0 * HD + n + 1], w0 * acc[mf][nf][1]);
            }
            if (w1 != 0.f) {
                atomicAdd(&out[(size_t)t1 * HD + n],     w1 * acc[mf][nf][2]);
                atomicAdd(&out[(size_t)t1 * HD + n + 1], w1 * acc[mf][nf][3]);
            }
        }
    }
}

// ---------------- launch ----------------
extern "C" void kernel_launch(void* const* d_in, const int* in_sizes, int n_in,
                              void* d_out, int out_size) {
    const float* x   = (const float*)d_in[0];  // [T, H]
    const float* gw  = (const float*)d_in[1];  // [E, H]
    const float* w1  = (const float*)d_in[2];  // [E, F, H]
    const float* w2  = (const float*)d_in[3];  // [E, H, F]
    const float* w3  = (const float*)d_in[4];  // [E, F, H]
    float* out       = (float*)d_out;          // [T*H] then logits [T*E]
    float* logits    = out + (size_t)TT * HD;

    cudaFuncSetAttribute(gemm1_mma, cudaFuncAttributeMaxDynamicSharedMemorySize, G1_SMEM);
    cudaFuncSetAttribute(gemm2_mma, cudaFuncAttributeMaxDynamicSharedMemorySize, G2_SMEM);

    uint2* w1h; cudaGetSymbolAddress((void**)&w1h, d_w1h);
    uint2* w3h; cudaGetSymbolAddress((void**)&w3h, d_w3h);
    uint2* w2h; cudaGetSymbolAddress((void**)&w2h, d_w2h);

    // prepass: compress+permute weights to fp16 fragment-major
    const int NWT = NE * NB1 * KB1 * 32;
    conv_w_kernel<<<NWT / 256, 256>>>(w1, w1h, NB1, KB1);
    conv_w_kernel<<<NWT / 256, 256>>>(w3, w3h, NB1, KB1);
    conv_w_kernel<<<(NE * NB2 * KB2 * 32) / 256, 256>>>(w2, w2h, NB2, KB2);

    // routing + output zero (merged)
    zero_all_kernel<<<(TT * (HD / 4) + 255) / 256, 256>>>((float4*)out);
    router_kernel<<<TT, 256>>>(x, gw, logits);
    offsets_kernel<<<1, 32>>>();
    assign_kernel<<<(TT + 255) / 256, 256>>>();
    gather_x_kernel<<<(SBLK * KB1 * 32 + 255) / 256, 256>>>(x);

    dim3 g1(TT / 128, FD / 64, NE);    // (32 m, 64 n, 8 e) — m fastest
    gemm1_mma<<<g1, 128, G1_SMEM>>>();

    dim3 g2(TT / 128, HD / 128, NE);   // (32 m, 8 n, 8 e) — m fastest
    gemm2_mma<<<g2, 128, G2_SMEM>>>(out);
}